// round 8
// baseline (speedup 1.0000x reference)
#include <cuda_runtime.h>
#include <cuda_bf16.h>
#include <math.h>
#include <stdint.h>

// Problem constants
#define BB   1024
#define SS   49
#define DD   128
#define HH   4
#define VV   100001
#define VV_PAD 100096            // 782 * 128
#define BS   (BB*SS)             // 50176
#define NEGV (-1e8f)

// =====================================================================
// scratch (device globals: no allocs allowed)
// =====================================================================
__device__ __align__(256) __nv_bfloat16 g_x   [BS * DD];              // embedded, bf16
__device__ __align__(256) float         g_qkv [BS * 3 * DD];          // q|k|v concat, ld=384
__device__ __align__(256) __nv_bfloat16 g_av  [BS * DD];              // attention out, bf16
__device__ __align__(256) float         g_enc [BS * DD];
__device__ __align__(256) __nv_bfloat16 g_p   [BB * DD];              // pooled, bf16
__device__ __align__(256) __nv_bfloat16 g_ws  [(size_t)VV_PAD * DD];  // w_score^T [n][k] bf16
__device__ __align__(256) __nv_bfloat16 g_w4  [4][DD * DD];           // wq,wk,wv,wo ^T bf16
__device__ __align__(256) float         g_b3  [3 * DD];               // bq|bk|bv concat

// =====================================================================
// PTX helpers
// =====================================================================
__device__ __forceinline__ void mma_bf16(float* c, const uint32_t* a, const uint32_t* b) {
    asm volatile(
        "mma.sync.aligned.m16n8k16.row.col.f32.bf16.bf16.f32 "
        "{%0,%1,%2,%3}, {%4,%5,%6,%7}, {%8,%9}, {%0,%1,%2,%3};"
        : "+f"(c[0]), "+f"(c[1]), "+f"(c[2]), "+f"(c[3])
        : "r"(a[0]), "r"(a[1]), "r"(a[2]), "r"(a[3]), "r"(b[0]), "r"(b[1]));
}
__device__ __forceinline__ uint32_t cvta_smem(const void* p) {
    uint32_t a;
    asm("{ .reg .u64 t; cvta.to.shared.u64 t, %1; cvt.u32.u64 %0, t; }"
        : "=r"(a) : "l"(p));
    return a;
}
__device__ __forceinline__ void ldsm_x4(uint32_t* r, uint32_t addr) {
    asm volatile("ldmatrix.sync.aligned.m8n8.x4.shared.b16 {%0,%1,%2,%3}, [%4];"
                 : "=r"(r[0]), "=r"(r[1]), "=r"(r[2]), "=r"(r[3]) : "r"(addr));
}

// smem tile geometry: rows x 128 bf16, padded row stride = 272 bytes
// row r starts at word 68r ≡ 4r (mod 32) -> each LDSM 8-row phase covers
// all 32 banks exactly -> conflict-free.
#define ROWB 272
#define TILE_B_SMEM (128 * ROWB)   // 34816
#define TILE_A_SMEM (64  * ROWB)   // 17408

// =====================================================================
// K1 (merged prep): embed+PE | w_score transpose | w4 transpose | bias3
// =====================================================================
#define PREP_EMBED  BS                     // 50176
#define PREP_WSV    (VV_PAD / 32)          // 3128
__global__ __launch_bounds__(128)
void prep_kernel(const int* __restrict__ seq, const int* __restrict__ sub,
                 const float* __restrict__ emb, const float* __restrict__ sgt,
                 const float* __restrict__ wscore,
                 const float* __restrict__ w0, const float* __restrict__ w1,
                 const float* __restrict__ w2, const float* __restrict__ w3,
                 const float* __restrict__ bq, const float* __restrict__ bk,
                 const float* __restrict__ bv,
                 __nv_bfloat16* __restrict__ x, __nv_bfloat16* __restrict__ ws,
                 __nv_bfloat16* __restrict__ w4, float* __restrict__ b3)
{
    __shared__ float st[32][129];
    const int bid = blockIdx.x;
    const int t = threadIdx.x;

    if (bid < PREP_EMBED) {
        int bs = bid;
        int s  = bs % SS;
        int item = seq[bs];
        int stype = sub[bs];
        float pe = (t & 1) ? cosf((float)s) : sinf((float)s);
        float v  = emb[(size_t)item * DD + t] + sgt[(size_t)stype * DD + t] + pe;
        x[(size_t)bs * DD + t] = __float2bfloat16(v);
        return;
    }
    if (bid < PREP_EMBED + PREP_WSV) {
        int n0 = (bid - PREP_EMBED) * 32;
        #pragma unroll
        for (int rep = 0; rep < 32; rep++) {
            int i = rep * 128 + t;
            int k = i >> 5, j = i & 31;
            int n = n0 + j;
            st[j][k] = (n < VV) ? wscore[(size_t)k * VV + n] : 0.f;
        }
        __syncthreads();
        #pragma unroll
        for (int rep = 0; rep < 32; rep++) {
            int i = rep * 128 + t;
            int nl = i >> 7, k = i & 127;
            ws[(size_t)(n0 + nl) * DD + k] = __float2bfloat16(st[nl][k]);
        }
        return;
    }
    if (bid < PREP_EMBED + PREP_WSV + 16) {
        int r  = bid - PREP_EMBED - PREP_WSV;
        int w  = r >> 2;
        int n0 = (r & 3) * 32;
        const float* W = (w == 0) ? w0 : (w == 1) ? w1 : (w == 2) ? w2 : w3;
        __nv_bfloat16* T = w4 + (size_t)w * DD * DD;
        #pragma unroll
        for (int rep = 0; rep < 32; rep++) {
            int i = rep * 128 + t;
            int k = i >> 5, j = i & 31;
            st[j][k] = W[(size_t)k * DD + n0 + j];
        }
        __syncthreads();
        #pragma unroll
        for (int rep = 0; rep < 32; rep++) {
            int i = rep * 128 + t;
            int nl = i >> 7, k = i & 127;
            T[(size_t)(n0 + nl) * DD + k] = __float2bfloat16(st[nl][k]);
        }
        return;
    }
    for (int i = t; i < 384; i += 128)
        b3[i] = (i < 128) ? bq[i] : (i < 256) ? bk[i - 128] : bv[i - 256];
}

// =====================================================================
// K2: bf16 tensor-core GEMM via mma.sync + ldmatrix (M-tile 64, N-tile 128)
// Double-buffered A across m_iters; B resident.
// =====================================================================
__device__ __forceinline__ void load_tile_128(char* s, const __nv_bfloat16* g, int t)
{
    #pragma unroll
    for (int i = 0; i < 8; i++) {
        int idx = i * 256 + t;
        int r = idx >> 4, seg = idx & 15;
        uint4 v = *reinterpret_cast<const uint4*>(g + (size_t)r * DD + seg * 8);
        *reinterpret_cast<uint4*>(s + r * ROWB + seg * 16) = v;
    }
}

__global__ __launch_bounds__(256, 3)
void mma_gemm(const __nv_bfloat16* __restrict__ A, const __nv_bfloat16* __restrict__ B,
              const float* __restrict__ bias, float* __restrict__ C,
              long long ldc, int nvalid, int m_iters)
{
    extern __shared__ char sm[];
    char* sB    = sm;
    char* sAbuf = sB + TILE_B_SMEM;                 // 2 x TILE_A_SMEM
    float* sbias = (float*)(sAbuf + 2 * TILE_A_SMEM);

    const int t = threadIdx.x;
    const int lane = t & 31;
    const int wid  = t >> 5;
    const int warp_m = wid >> 2;        // 0..1  (32 rows each)
    const int warp_n = wid & 3;         // 0..3  (32 cols each)
    const int n0 = blockIdx.x * 128;

    load_tile_128(sB, B + (size_t)n0 * DD, t);
    if (t < 128) {
        int n = n0 + t;
        sbias[t] = (n < nvalid) ? bias[n] : 0.f;
    }
    {   // first A tile
        const __nv_bfloat16* g = A + (size_t)(blockIdx.y * m_iters) * 64 * DD;
        #pragma unroll
        for (int i = 0; i < 4; i++) {
            int idx = i * 256 + t;
            int r = idx >> 4, seg = idx & 15;
            uint4 v = *reinterpret_cast<const uint4*>(g + (size_t)r * DD + seg * 8);
            *reinterpret_cast<uint4*>(sAbuf + r * ROWB + seg * 16) = v;
        }
    }
    __syncthreads();

    // ---- ldmatrix lane addressing ----
    const int quad = lane >> 3, j = lane & 7;
    // A x4: quads -> (m0-7,k0-7),(m8-15,k0-7),(m0-7,k8-15),(m8-15,k8-15)
    const uint32_t aLane = (uint32_t)((warp_m * 32 + (quad & 1) * 8 + j) * ROWB
                                      + (quad >> 1) * 16);
    const uint32_t aSm0 = cvta_smem(sAbuf) + aLane;
    // B x4: quads -> (ni0,k0-7),(ni0,k8-15),(ni1,k0-7),(ni1,k8-15)
    const uint32_t bAddr = cvta_smem(sB)
                         + (uint32_t)((warp_n * 32 + (quad >> 1) * 8 + j) * ROWB
                                      + (quad & 1) * 16);

    const int frow = lane >> 2;
    // vectorized stores need 8B-aligned row bases -> ldc must be even
    const bool fullN = (n0 + 128 <= nvalid) && ((ldc & 1LL) == 0LL);
    int cur = 0;

    for (int iter = 0; iter < m_iters; iter++) {
        const int m0 = (blockIdx.y * m_iters + iter) * 64;
        const bool has_next = (iter + 1 < m_iters);

        // prefetch next A tile into registers (overlaps with MMA compute)
        uint4 pre[4];
        if (has_next) {
            const __nv_bfloat16* gn = A + (size_t)(m0 + 64) * DD;
            #pragma unroll
            for (int i = 0; i < 4; i++) {
                int idx = i * 256 + t;
                int r = idx >> 4, seg = idx & 15;
                pre[i] = *reinterpret_cast<const uint4*>(gn + (size_t)r * DD + seg * 8);
            }
        }

        const uint32_t aAddr = aSm0 + (uint32_t)(cur * TILE_A_SMEM);

        float acc[2][4][4];
        #pragma unroll
        for (int mi = 0; mi < 2; mi++)
            #pragma unroll
            for (int ni = 0; ni < 4; ni++)
                #pragma unroll
                for (int e = 0; e < 4; e++) acc[mi][ni][e] = 0.f;

        #pragma unroll
        for (int kb = 0; kb < 8; kb++) {
            const uint32_t ko = kb * 32;
            uint32_t a0[4], a1[4], b01[4], b23[4];
            ldsm_x4(a0,  aAddr + ko);                      // mi=0
            ldsm_x4(a1,  aAddr + ko + 16 * ROWB);          // mi=1
            ldsm_x4(b01, bAddr + ko);                      // ni=0,1
            ldsm_x4(b23, bAddr + ko + 16 * ROWB);          // ni=2,3
            mma_bf16(acc[0][0], a0, b01);     mma_bf16(acc[0][1], a0, b01 + 2);
            mma_bf16(acc[0][2], a0, b23);     mma_bf16(acc[0][3], a0, b23 + 2);
            mma_bf16(acc[1][0], a1, b01);     mma_bf16(acc[1][1], a1, b01 + 2);
            mma_bf16(acc[1][2], a1, b23);     mma_bf16(acc[1][3], a1, b23 + 2);
        }

        if (has_next) {
            char* sAn = sAbuf + (cur ^ 1) * TILE_A_SMEM;
            #pragma unroll
            for (int i = 0; i < 4; i++) {
                int idx = i * 256 + t;
                int r = idx >> 4, seg = idx & 15;
                *reinterpret_cast<uint4*>(sAn + r * ROWB + seg * 16) = pre[i];
            }
            __syncthreads();
            cur ^= 1;
        }

        // ---- epilogue ----
        #pragma unroll
        for (int mi = 0; mi < 2; mi++) {
            const int r0 = m0 + warp_m * 32 + mi * 16 + frow;
            float* crow0 = C + (long long)r0 * ldc;
            float* crow1 = C + (long long)(r0 + 8) * ldc;
            if (fullN) {
                #pragma unroll
                for (int ni = 0; ni < 4; ni++) {
                    const int nl = warp_n * 32 + ni * 8 + (lane & 3) * 2;
                    const int n  = n0 + nl;
                    float2 s0 = make_float2(acc[mi][ni][0] + sbias[nl],
                                            acc[mi][ni][1] + sbias[nl + 1]);
                    float2 s1 = make_float2(acc[mi][ni][2] + sbias[nl],
                                            acc[mi][ni][3] + sbias[nl + 1]);
                    *reinterpret_cast<float2*>(crow0 + n) = s0;
                    *reinterpret_cast<float2*>(crow1 + n) = s1;
                }
            } else {
                #pragma unroll
                for (int ni = 0; ni < 4; ni++) {
                    const int nl = warp_n * 32 + ni * 8 + (lane & 3) * 2;
                    const int n  = n0 + nl;
                    const float b0 = sbias[nl], b1 = sbias[nl + 1];
                    if (n < nvalid) {
                        crow0[n] = acc[mi][ni][0] + b0;
                        crow1[n] = acc[mi][ni][2] + b0;
                    }
                    if (n + 1 < nvalid) {
                        crow0[n + 1] = acc[mi][ni][1] + b1;
                        crow1[n + 1] = acc[mi][ni][3] + b1;
                    }
                }
            }
        }
    }
}

// =====================================================================
// K3: attention, one block per (b,h); float4-vectorized smem
// =====================================================================
__global__ __launch_bounds__(256)
void attn_kernel(const float* __restrict__ qkv, const int* __restrict__ seq,
                 __nv_bfloat16* __restrict__ av)
{
    __shared__ float sq[SS][36], sk[SS][36], sv[SS][36];
    __shared__ float sc[SS][52];
    __shared__ int   spad[SS];

    int b = blockIdx.x >> 2;
    int h = blockIdx.x & 3;
    int tid = threadIdx.x;

    for (int idx = tid; idx < SS * 8; idx += 256) {
        int s = idx >> 3, c = idx & 7;
        size_t base = ((size_t)(b * SS + s)) * 384 + h * 32 + c * 4;
        float4 q4 = *reinterpret_cast<const float4*>(qkv + base);
        float4 k4 = *reinterpret_cast<const float4*>(qkv + base + 128);
        float4 v4 = *reinterpret_cast<const float4*>(qkv + base + 256);
        *reinterpret_cast<float4*>(&sq[s][c * 4]) = q4;
        *reinterpret_cast<float4*>(&sk[s][c * 4]) = k4;
        *reinterpret_cast<float4*>(&sv[s][c * 4]) = v4;
    }
    if (tid < SS) spad[tid] = (seq[b * SS + tid] == 0);
    __syncthreads();

    for (int idx = tid; idx < SS * SS; idx += 256) {
        int qi = idx / SS;
        int kj = idx - qi * SS;
        const float4* q4 = reinterpret_cast<const float4*>(&sq[qi][0]);
        const float4* k4 = reinterpret_cast<const float4*>(&sk[kj][0]);
        float acc = 0.f;
        #pragma unroll
        for (int w = 0; w < 8; w++) {
            float4 a = q4[w], c = k4[w];
            acc += a.x * c.x + a.y * c.y + a.z * c.z + a.w * c.w;
        }
        acc *= (1.0f / 32.0f);
        if (spad[qi] | spad[kj]) acc = NEGV;
        sc[qi][kj] = acc;
    }
    __syncthreads();

    int wid = tid >> 5, lane = tid & 31;
    for (int r = wid; r < SS; r += 8) {
        float m = -INFINITY;
        for (int j = lane; j < SS; j += 32) m = fmaxf(m, sc[r][j]);
        #pragma unroll
        for (int o = 16; o; o >>= 1) m = fmaxf(m, __shfl_xor_sync(0xffffffffu, m, o));
        float sum = 0.f;
        for (int j = lane; j < SS; j += 32) {
            float e = expf(sc[r][j] - m);
            sc[r][j] = e;
            sum += e;
        }
        #pragma unroll
        for (int o = 16; o; o >>= 1) sum += __shfl_xor_sync(0xffffffffu, sum, o);
        float inv = 1.0f / sum;
        for (int j = lane; j < SS; j += 32) sc[r][j] *= inv;
    }
    __syncthreads();

    for (int idx = tid; idx < SS * 8; idx += 256) {
        int s = idx >> 3, c = idx & 7;
        float4 acc = make_float4(0.f, 0.f, 0.f, 0.f);
        #pragma unroll 7
        for (int j = 0; j < SS; j++) {
            float p = sc[s][j];
            float4 v4 = *reinterpret_cast<const float4*>(&sv[j][c * 4]);
            acc.x += p * v4.x; acc.y += p * v4.y;
            acc.z += p * v4.z; acc.w += p * v4.w;
        }
        size_t o = ((size_t)(b * SS + s)) * DD + h * 32 + c * 4;
        __nv_bfloat162 p0, p1;
        p0.x = __float2bfloat16(acc.x); p0.y = __float2bfloat16(acc.y);
        p1.x = __float2bfloat16(acc.z); p1.y = __float2bfloat16(acc.w);
        *reinterpret_cast<__nv_bfloat162*>(av + o)     = p0;
        *reinterpret_cast<__nv_bfloat162*>(av + o + 2) = p1;
    }
}

// =====================================================================
// K4: SelfEnc pooling, one block per batch; emits bf16
// =====================================================================
__global__ __launch_bounds__(128)
void pool_kernel(const float* __restrict__ enc, const float* __restrict__ w_enc,
                 const float* __restrict__ b_enc, __nv_bfloat16* __restrict__ p)
{
    __shared__ float se[SS][DD];
    __shared__ float swt[SS];
    __shared__ float swe[DD];
    int b = blockIdx.x;
    int tid = threadIdx.x;

    swe[tid] = w_enc[tid];
    for (int idx = tid; idx < SS * DD; idx += 128)
        se[idx >> 7][idx & 127] = enc[(size_t)b * SS * DD + idx];
    __syncthreads();

    int wid = tid >> 5, lane = tid & 31;
    for (int s = wid; s < SS; s += 4) {
        float acc = 0.f;
        #pragma unroll
        for (int d = lane; d < DD; d += 32) acc += se[s][d] * swe[d];
        #pragma unroll
        for (int o = 16; o; o >>= 1) acc += __shfl_xor_sync(0xffffffffu, acc, o);
        if (lane == 0) swt[s] = acc + b_enc[0];
    }
    __syncthreads();

    float acc = 0.f;
    #pragma unroll
    for (int s = 0; s < SS; s++) acc += swt[s] * se[s][tid];
    p[b * DD + tid] = __float2bfloat16(acc);
}

// =====================================================================
// K5: consumed-item mask scatter
// =====================================================================
__global__ void mask_kernel(const int* __restrict__ seq, float* __restrict__ out)
{
    int b = blockIdx.x;
    int s = threadIdx.x;
    if (s < SS) out[(size_t)b * VV + seq[b * SS + s]] = NEGV;
}

// =====================================================================
// launch
// =====================================================================
extern "C" void kernel_launch(void* const* d_in, const int* in_sizes, int n_in,
                              void* d_out, int out_size)
{
    const int*   seq    = (const int*)  d_in[0];
    const int*   subty  = (const int*)  d_in[1];
    const float* emb    = (const float*)d_in[2];
    const float* sgt    = (const float*)d_in[3];
    const float* wq     = (const float*)d_in[4];
    const float* bq     = (const float*)d_in[5];
    const float* wk     = (const float*)d_in[6];
    const float* bk     = (const float*)d_in[7];
    const float* wv     = (const float*)d_in[8];
    const float* bv     = (const float*)d_in[9];
    const float* wo     = (const float*)d_in[10];
    const float* bo     = (const float*)d_in[11];
    const float* w_enc  = (const float*)d_in[12];
    const float* b_enc  = (const float*)d_in[13];
    const float* wscore = (const float*)d_in[14];
    const float* bscore = (const float*)d_in[15];
    float* out = (float*)d_out;

    __nv_bfloat16 *x, *av, *p, *ws, *w4;
    float *qkv, *enc, *b3;
    cudaGetSymbolAddress((void**)&x,    g_x);
    cudaGetSymbolAddress((void**)&qkv,  g_qkv);
    cudaGetSymbolAddress((void**)&av,   g_av);
    cudaGetSymbolAddress((void**)&enc,  g_enc);
    cudaGetSymbolAddress((void**)&p,    g_p);
    cudaGetSymbolAddress((void**)&ws,   g_ws);
    cudaGetSymbolAddress((void**)&w4,   g_w4);
    cudaGetSymbolAddress((void**)&b3,   g_b3);

    const int GEMM_SMEM = TILE_B_SMEM + 2 * TILE_A_SMEM + 512;   // 70144
    cudaFuncSetAttribute(mma_gemm, cudaFuncAttributeMaxDynamicSharedMemorySize, GEMM_SMEM);

    // 1) merged prep: embed+PE, weight transposes, bias concat
    prep_kernel<<<PREP_EMBED + PREP_WSV + 16 + 1, 128>>>(
        seq, subty, emb, sgt, wscore, wq, wk, wv, wo, bq, bk, bv,
        x, ws, w4, b3);

    // 2) fused QKV projection: B = [wq^T|wk^T|wv^T] (384 rows), C ldc=384
    mma_gemm<<<dim3(3, BS / 64), 256, GEMM_SMEM>>>(x, w4, b3, qkv, 384, 384, 1);

    // 3) attention (emits bf16 av)
    attn_kernel<<<BB * HH, 256>>>(qkv, seq, av);

    // 4) output projection
    mma_gemm<<<dim3(1, BS / 64), 256, GEMM_SMEM>>>(av, w4 + 3 * DD * DD,
                                                   bo, enc, DD, DD, 1);

    // 5) pooling (emits bf16 p)
    pool_kernel<<<BB, 128>>>(enc, w_enc, b_enc, p);

    // 6) novelty scores: grid (782 n-tiles, 4 m-groups), 4 M-tiles each
    mma_gemm<<<dim3(VV_PAD / 128, 4), 256, GEMM_SMEM>>>(p, ws, bscore, out,
                                                        (long long)VV, VV, 4);

    // 7) consumed mask
    mask_kernel<<<BB, 64>>>(seq, out);
}

// round 9
// speedup vs baseline: 1.2905x; 1.2905x over previous
#include <cuda_runtime.h>
#include <cuda_bf16.h>
#include <math.h>
#include <stdint.h>

// Problem constants
#define BB   1024
#define SS   49
#define DD   128
#define HH   4
#define VV   100001
#define VV_PAD 100096            // 782 * 128 = 391 * 256
#define BS   (BB*SS)             // 50176
#define NEGV (-1e8f)

// =====================================================================
// scratch (device globals: no allocs allowed)
// =====================================================================
__device__ __align__(256) __nv_bfloat16 g_x   [BS * DD];              // embedded, bf16
__device__ __align__(256) float         g_qkv [BS * 3 * DD];          // q|k|v concat, ld=384
__device__ __align__(256) __nv_bfloat16 g_av  [BS * DD];              // attention out, bf16
__device__ __align__(256) float         g_enc [BS * DD];
__device__ __align__(256) __nv_bfloat16 g_p   [BB * DD];              // pooled, bf16
__device__ __align__(256) __nv_bfloat16 g_ws  [(size_t)VV_PAD * DD];  // w_score^T [n][k] bf16
__device__ __align__(256) __nv_bfloat16 g_w4  [4][DD * DD];           // wq,wk,wv,wo ^T bf16
__device__ __align__(256) float         g_b3  [3 * DD];               // bq|bk|bv concat

// =====================================================================
// PTX helpers
// =====================================================================
__device__ __forceinline__ void mma_bf16(float* c, const uint32_t* a, const uint32_t* b) {
    asm volatile(
        "mma.sync.aligned.m16n8k16.row.col.f32.bf16.bf16.f32 "
        "{%0,%1,%2,%3}, {%4,%5,%6,%7}, {%8,%9}, {%0,%1,%2,%3};"
        : "+f"(c[0]), "+f"(c[1]), "+f"(c[2]), "+f"(c[3])
        : "r"(a[0]), "r"(a[1]), "r"(a[2]), "r"(a[3]), "r"(b[0]), "r"(b[1]));
}
__device__ __forceinline__ uint32_t cvta_smem(const void* p) {
    uint32_t a;
    asm("{ .reg .u64 t; cvta.to.shared.u64 t, %1; cvt.u32.u64 %0, t; }"
        : "=r"(a) : "l"(p));
    return a;
}
__device__ __forceinline__ void ldsm_x4(uint32_t* r, uint32_t addr) {
    asm volatile("ldmatrix.sync.aligned.m8n8.x4.shared.b16 {%0,%1,%2,%3}, [%4];"
                 : "=r"(r[0]), "=r"(r[1]), "=r"(r[2]), "=r"(r[3]) : "r"(addr));
}
__device__ __forceinline__ void cp16(uint32_t s, const void* g) {
    asm volatile("cp.async.ca.shared.global [%0], [%1], 16;" :: "r"(s), "l"(g));
}
#define CP_COMMIT() asm volatile("cp.async.commit_group;" ::: "memory")
#define CP_WAIT0()  asm volatile("cp.async.wait_group 0;" ::: "memory")

// smem tile geometry: rows x 128 bf16, padded row stride = 272 bytes
// row r starts at word 68r ≡ 4r (mod 32) -> each LDSM 8-row phase covers
// all 32 banks exactly -> conflict-free.
#define ROWB 272
#define TILE_A_SMEM (64 * ROWB)    // 17408

// =====================================================================
// K1 (merged prep): embed+PE | w_score transpose | w4 transpose | bias3
// =====================================================================
#define PREP_EMBED  BS                     // 50176
#define PREP_WSV    (VV_PAD / 32)          // 3128
__global__ __launch_bounds__(128)
void prep_kernel(const int* __restrict__ seq, const int* __restrict__ sub,
                 const float* __restrict__ emb, const float* __restrict__ sgt,
                 const float* __restrict__ wscore,
                 const float* __restrict__ w0, const float* __restrict__ w1,
                 const float* __restrict__ w2, const float* __restrict__ w3,
                 const float* __restrict__ bq, const float* __restrict__ bk,
                 const float* __restrict__ bv,
                 __nv_bfloat16* __restrict__ x, __nv_bfloat16* __restrict__ ws,
                 __nv_bfloat16* __restrict__ w4, float* __restrict__ b3)
{
    __shared__ float st[32][129];
    const int bid = blockIdx.x;
    const int t = threadIdx.x;

    if (bid < PREP_EMBED) {
        int bs = bid;
        int s  = bs % SS;
        int item = seq[bs];
        int stype = sub[bs];
        float pe = (t & 1) ? cosf((float)s) : sinf((float)s);
        float v  = emb[(size_t)item * DD + t] + sgt[(size_t)stype * DD + t] + pe;
        x[(size_t)bs * DD + t] = __float2bfloat16(v);
        return;
    }
    if (bid < PREP_EMBED + PREP_WSV) {
        int n0 = (bid - PREP_EMBED) * 32;
        #pragma unroll
        for (int rep = 0; rep < 32; rep++) {
            int i = rep * 128 + t;
            int k = i >> 5, j = i & 31;
            int n = n0 + j;
            st[j][k] = (n < VV) ? wscore[(size_t)k * VV + n] : 0.f;
        }
        __syncthreads();
        #pragma unroll
        for (int rep = 0; rep < 32; rep++) {
            int i = rep * 128 + t;
            int nl = i >> 7, k = i & 127;
            ws[(size_t)(n0 + nl) * DD + k] = __float2bfloat16(st[nl][k]);
        }
        return;
    }
    if (bid < PREP_EMBED + PREP_WSV + 16) {
        int r  = bid - PREP_EMBED - PREP_WSV;
        int w  = r >> 2;
        int n0 = (r & 3) * 32;
        const float* W = (w == 0) ? w0 : (w == 1) ? w1 : (w == 2) ? w2 : w3;
        __nv_bfloat16* T = w4 + (size_t)w * DD * DD;
        #pragma unroll
        for (int rep = 0; rep < 32; rep++) {
            int i = rep * 128 + t;
            int k = i >> 5, j = i & 31;
            st[j][k] = W[(size_t)k * DD + n0 + j];
        }
        __syncthreads();
        #pragma unroll
        for (int rep = 0; rep < 32; rep++) {
            int i = rep * 128 + t;
            int nl = i >> 7, k = i & 127;
            T[(size_t)(n0 + nl) * DD + k] = __float2bfloat16(st[nl][k]);
        }
        return;
    }
    for (int i = t; i < 384; i += 128)
        b3[i] = (i < 128) ? bq[i] : (i < 256) ? bk[i - 128] : bv[i - 256];
}

// =====================================================================
// K2: bf16 tensor-core GEMM, templated on warp columns (32 or 64)
// CTA tile: 64(M) x 4*WCOLS(N).  cp.async loads, double-buffered A.
// =====================================================================
template<int WCOLS>
__global__ __launch_bounds__(256, (WCOLS == 32) ? 3 : 2)
void mma_gemm(const __nv_bfloat16* __restrict__ A, const __nv_bfloat16* __restrict__ B,
              const float* __restrict__ bias, float* __restrict__ C,
              long long ldc, int nvalid, int m_iters)
{
    constexpr int NTILE = WCOLS * 4;
    constexpr int NI    = WCOLS / 8;       // 8-col groups per warp
    constexpr int NGRP  = WCOLS / 32;      // 32-col LDSM groups per warp
    constexpr int TILE_B_SM = NTILE * ROWB;

    extern __shared__ char sm[];
    char* sB    = sm;
    char* sAbuf = sB + TILE_B_SM;                   // 2 x TILE_A_SMEM
    float* sbias = (float*)(sAbuf + 2 * TILE_A_SMEM);

    const int t = threadIdx.x;
    const int lane = t & 31;
    const int wid  = t >> 5;
    const int warp_m = wid >> 2;        // 0..1  (32 rows each)
    const int warp_n = wid & 3;         // 0..3  (WCOLS cols each)
    const int n0 = blockIdx.x * NTILE;

    const uint32_t sBu = cvta_smem(sB);
    const uint32_t sAu = cvta_smem(sAbuf);

    // ---- async load B tile + first A tile ----
    {
        const __nv_bfloat16* gB = B + (size_t)n0 * DD;
        #pragma unroll
        for (int i = 0; i < NTILE / 16; i++) {
            int idx = i * 256 + t;
            int r = idx >> 4, seg = idx & 15;
            cp16(sBu + r * ROWB + seg * 16, gB + (size_t)r * DD + seg * 8);
        }
        const __nv_bfloat16* gA = A + (size_t)(blockIdx.y * m_iters) * 64 * DD;
        #pragma unroll
        for (int i = 0; i < 4; i++) {
            int idx = i * 256 + t;
            int r = idx >> 4, seg = idx & 15;
            cp16(sAu + r * ROWB + seg * 16, gA + (size_t)r * DD + seg * 8);
        }
        CP_COMMIT();
        #pragma unroll
        for (int i = 0; i < NTILE / 256 + 1; i++) {
            int n = i * 256 + t;
            if (n < NTILE) sbias[n] = (n0 + n < nvalid) ? bias[n0 + n] : 0.f;
        }
        CP_WAIT0();
    }
    __syncthreads();

    // ---- ldmatrix lane addressing ----
    const int quad = lane >> 3, j = lane & 7;
    // A x4: quads -> (m0-7,k0-7),(m8-15,k0-7),(m0-7,k8-15),(m8-15,k8-15)
    const uint32_t aLane = (uint32_t)((warp_m * 32 + (quad & 1) * 8 + j) * ROWB
                                      + (quad >> 1) * 16);
    // B x4 per 32-col group g: quads -> (c0-7,k0-7),(c0-7,k8-15),(c8-15,k0-7),(c8-15,k8-15)
    const uint32_t bLane = sBu
                         + (uint32_t)((warp_n * WCOLS + (quad >> 1) * 8 + j) * ROWB
                                      + (quad & 1) * 16);

    const int frow = lane >> 2;
    const bool fullN = (n0 + NTILE <= nvalid) && ((ldc & 1LL) == 0LL);
    int cur = 0;

    for (int iter = 0; iter < m_iters; iter++) {
        const int m0 = (blockIdx.y * m_iters + iter) * 64;
        const bool has_next = (iter + 1 < m_iters);

        // async prefetch next A tile into the other buffer (overlaps MMA)
        if (has_next) {
            const __nv_bfloat16* gn = A + (size_t)(m0 + 64) * DD;
            const uint32_t dst = sAu + (uint32_t)((cur ^ 1) * TILE_A_SMEM);
            #pragma unroll
            for (int i = 0; i < 4; i++) {
                int idx = i * 256 + t;
                int r = idx >> 4, seg = idx & 15;
                cp16(dst + r * ROWB + seg * 16, gn + (size_t)r * DD + seg * 8);
            }
            CP_COMMIT();
        }

        const uint32_t aAddr = aLane + sAu + (uint32_t)(cur * TILE_A_SMEM);

        float acc[2][NI][4];
        #pragma unroll
        for (int mi = 0; mi < 2; mi++)
            #pragma unroll
            for (int ni = 0; ni < NI; ni++)
                #pragma unroll
                for (int e = 0; e < 4; e++) acc[mi][ni][e] = 0.f;

        #pragma unroll
        for (int kb = 0; kb < 8; kb++) {
            const uint32_t ko = kb * 32;
            uint32_t a0[4], a1[4];
            ldsm_x4(a0, aAddr + ko);                 // mi=0 (m rows 0-15)
            ldsm_x4(a1, aAddr + ko + 16 * ROWB);     // mi=1 (m rows 16-31)
            uint32_t bf[NGRP * 2][4];
            #pragma unroll
            for (int g = 0; g < NGRP; g++) {
                ldsm_x4(bf[g * 2],     bLane + ko + (uint32_t)(g * 32 * ROWB));
                ldsm_x4(bf[g * 2 + 1], bLane + ko + (uint32_t)((g * 32 + 16) * ROWB));
            }
            #pragma unroll
            for (int g = 0; g < NGRP; g++) {
                mma_bf16(acc[0][g * 4 + 0], a0, bf[g * 2]);
                mma_bf16(acc[0][g * 4 + 1], a0, bf[g * 2] + 2);
                mma_bf16(acc[0][g * 4 + 2], a0, bf[g * 2 + 1]);
                mma_bf16(acc[0][g * 4 + 3], a0, bf[g * 2 + 1] + 2);
                mma_bf16(acc[1][g * 4 + 0], a1, bf[g * 2]);
                mma_bf16(acc[1][g * 4 + 1], a1, bf[g * 2] + 2);
                mma_bf16(acc[1][g * 4 + 2], a1, bf[g * 2 + 1]);
                mma_bf16(acc[1][g * 4 + 3], a1, bf[g * 2 + 1] + 2);
            }
        }

        // ---- epilogue (overlaps the in-flight cp.async) ----
        #pragma unroll
        for (int mi = 0; mi < 2; mi++) {
            const int r0 = m0 + warp_m * 32 + mi * 16 + frow;
            float* crow0 = C + (long long)r0 * ldc;
            float* crow1 = C + (long long)(r0 + 8) * ldc;
            if (fullN) {
                #pragma unroll
                for (int ni = 0; ni < NI; ni++) {
                    const int nl = warp_n * WCOLS + ni * 8 + (lane & 3) * 2;
                    const int n  = n0 + nl;
                    float2 s0 = make_float2(acc[mi][ni][0] + sbias[nl],
                                            acc[mi][ni][1] + sbias[nl + 1]);
                    float2 s1 = make_float2(acc[mi][ni][2] + sbias[nl],
                                            acc[mi][ni][3] + sbias[nl + 1]);
                    *reinterpret_cast<float2*>(crow0 + n) = s0;
                    *reinterpret_cast<float2*>(crow1 + n) = s1;
                }
            } else {
                #pragma unroll
                for (int ni = 0; ni < NI; ni++) {
                    const int nl = warp_n * WCOLS + ni * 8 + (lane & 3) * 2;
                    const int n  = n0 + nl;
                    const float b0 = sbias[nl], b1 = sbias[nl + 1];
                    if (n < nvalid) {
                        crow0[n] = acc[mi][ni][0] + b0;
                        crow1[n] = acc[mi][ni][2] + b0;
                    }
                    if (n + 1 < nvalid) {
                        crow0[n + 1] = acc[mi][ni][1] + b1;
                        crow1[n + 1] = acc[mi][ni][3] + b1;
                    }
                }
            }
        }

        if (has_next) {
            CP_WAIT0();
            __syncthreads();
            cur ^= 1;
        }
    }
}

// =====================================================================
// K3: attention, one block per (b,h); float4-vectorized smem
// =====================================================================
__global__ __launch_bounds__(256)
void attn_kernel(const float* __restrict__ qkv, const int* __restrict__ seq,
                 __nv_bfloat16* __restrict__ av)
{
    __shared__ float sq[SS][36], sk[SS][36], sv[SS][36];
    __shared__ float sc[SS][52];
    __shared__ int   spad[SS];

    int b = blockIdx.x >> 2;
    int h = blockIdx.x & 3;
    int tid = threadIdx.x;

    for (int idx = tid; idx < SS * 8; idx += 256) {
        int s = idx >> 3, c = idx & 7;
        size_t base = ((size_t)(b * SS + s)) * 384 + h * 32 + c * 4;
        float4 q4 = *reinterpret_cast<const float4*>(qkv + base);
        float4 k4 = *reinterpret_cast<const float4*>(qkv + base + 128);
        float4 v4 = *reinterpret_cast<const float4*>(qkv + base + 256);
        *reinterpret_cast<float4*>(&sq[s][c * 4]) = q4;
        *reinterpret_cast<float4*>(&sk[s][c * 4]) = k4;
        *reinterpret_cast<float4*>(&sv[s][c * 4]) = v4;
    }
    if (tid < SS) spad[tid] = (seq[b * SS + tid] == 0);
    __syncthreads();

    for (int idx = tid; idx < SS * SS; idx += 256) {
        int qi = idx / SS;
        int kj = idx - qi * SS;
        const float4* q4 = reinterpret_cast<const float4*>(&sq[qi][0]);
        const float4* k4 = reinterpret_cast<const float4*>(&sk[kj][0]);
        float acc = 0.f;
        #pragma unroll
        for (int w = 0; w < 8; w++) {
            float4 a = q4[w], c = k4[w];
            acc += a.x * c.x + a.y * c.y + a.z * c.z + a.w * c.w;
        }
        acc *= (1.0f / 32.0f);
        if (spad[qi] | spad[kj]) acc = NEGV;
        sc[qi][kj] = acc;
    }
    __syncthreads();

    int wid = tid >> 5, lane = tid & 31;
    for (int r = wid; r < SS; r += 8) {
        float m = -INFINITY;
        for (int j = lane; j < SS; j += 32) m = fmaxf(m, sc[r][j]);
        #pragma unroll
        for (int o = 16; o; o >>= 1) m = fmaxf(m, __shfl_xor_sync(0xffffffffu, m, o));
        float sum = 0.f;
        for (int j = lane; j < SS; j += 32) {
            float e = expf(sc[r][j] - m);
            sc[r][j] = e;
            sum += e;
        }
        #pragma unroll
        for (int o = 16; o; o >>= 1) sum += __shfl_xor_sync(0xffffffffu, sum, o);
        float inv = 1.0f / sum;
        for (int j = lane; j < SS; j += 32) sc[r][j] *= inv;
    }
    __syncthreads();

    for (int idx = tid; idx < SS * 8; idx += 256) {
        int s = idx >> 3, c = idx & 7;
        float4 acc = make_float4(0.f, 0.f, 0.f, 0.f);
        #pragma unroll 7
        for (int j = 0; j < SS; j++) {
            float p = sc[s][j];
            float4 v4 = *reinterpret_cast<const float4*>(&sv[j][c * 4]);
            acc.x += p * v4.x; acc.y += p * v4.y;
            acc.z += p * v4.z; acc.w += p * v4.w;
        }
        size_t o = ((size_t)(b * SS + s)) * DD + h * 32 + c * 4;
        __nv_bfloat162 p0, p1;
        p0.x = __float2bfloat16(acc.x); p0.y = __float2bfloat16(acc.y);
        p1.x = __float2bfloat16(acc.z); p1.y = __float2bfloat16(acc.w);
        *reinterpret_cast<__nv_bfloat162*>(av + o)     = p0;
        *reinterpret_cast<__nv_bfloat162*>(av + o + 2) = p1;
    }
}

// =====================================================================
// K4: SelfEnc pooling, one block per batch; emits bf16
// =====================================================================
__global__ __launch_bounds__(128)
void pool_kernel(const float* __restrict__ enc, const float* __restrict__ w_enc,
                 const float* __restrict__ b_enc, __nv_bfloat16* __restrict__ p)
{
    __shared__ float se[SS][DD];
    __shared__ float swt[SS];
    __shared__ float swe[DD];
    int b = blockIdx.x;
    int tid = threadIdx.x;

    swe[tid] = w_enc[tid];
    for (int idx = tid; idx < SS * DD; idx += 128)
        se[idx >> 7][idx & 127] = enc[(size_t)b * SS * DD + idx];
    __syncthreads();

    int wid = tid >> 5, lane = tid & 31;
    for (int s = wid; s < SS; s += 4) {
        float acc = 0.f;
        #pragma unroll
        for (int d = lane; d < DD; d += 32) acc += se[s][d] * swe[d];
        #pragma unroll
        for (int o = 16; o; o >>= 1) acc += __shfl_xor_sync(0xffffffffu, acc, o);
        if (lane == 0) swt[s] = acc + b_enc[0];
    }
    __syncthreads();

    float acc = 0.f;
    #pragma unroll
    for (int s = 0; s < SS; s++) acc += swt[s] * se[s][tid];
    p[b * DD + tid] = __float2bfloat16(acc);
}

// =====================================================================
// K5: consumed-item mask scatter
// =====================================================================
__global__ void mask_kernel(const int* __restrict__ seq, float* __restrict__ out)
{
    int b = blockIdx.x;
    int s = threadIdx.x;
    if (s < SS) out[(size_t)b * VV + seq[b * SS + s]] = NEGV;
}

// =====================================================================
// launch
// =====================================================================
extern "C" void kernel_launch(void* const* d_in, const int* in_sizes, int n_in,
                              void* d_out, int out_size)
{
    const int*   seq    = (const int*)  d_in[0];
    const int*   subty  = (const int*)  d_in[1];
    const float* emb    = (const float*)d_in[2];
    const float* sgt    = (const float*)d_in[3];
    const float* wq     = (const float*)d_in[4];
    const float* bq     = (const float*)d_in[5];
    const float* wk     = (const float*)d_in[6];
    const float* bk     = (const float*)d_in[7];
    const float* wv     = (const float*)d_in[8];
    const float* bv     = (const float*)d_in[9];
    const float* wo     = (const float*)d_in[10];
    const float* bo     = (const float*)d_in[11];
    const float* w_enc  = (const float*)d_in[12];
    const float* b_enc  = (const float*)d_in[13];
    const float* wscore = (const float*)d_in[14];
    const float* bscore = (const float*)d_in[15];
    float* out = (float*)d_out;

    __nv_bfloat16 *x, *av, *p, *ws, *w4;
    float *qkv, *enc, *b3;
    cudaGetSymbolAddress((void**)&x,    g_x);
    cudaGetSymbolAddress((void**)&qkv,  g_qkv);
    cudaGetSymbolAddress((void**)&av,   g_av);
    cudaGetSymbolAddress((void**)&enc,  g_enc);
    cudaGetSymbolAddress((void**)&p,    g_p);
    cudaGetSymbolAddress((void**)&ws,   g_ws);
    cudaGetSymbolAddress((void**)&w4,   g_w4);
    cudaGetSymbolAddress((void**)&b3,   g_b3);

    const int SMEM32 = 128 * ROWB + 2 * TILE_A_SMEM + 512;    // 70144
    const int SMEM64 = 256 * ROWB + 2 * TILE_A_SMEM + 1024;   // 105472
    cudaFuncSetAttribute(mma_gemm<32>, cudaFuncAttributeMaxDynamicSharedMemorySize, SMEM32);
    cudaFuncSetAttribute(mma_gemm<64>, cudaFuncAttributeMaxDynamicSharedMemorySize, SMEM64);

    // 1) merged prep: embed+PE, weight transposes, bias concat
    prep_kernel<<<PREP_EMBED + PREP_WSV + 16 + 1, 128>>>(
        seq, subty, emb, sgt, wscore, wq, wk, wv, wo, bq, bk, bv,
        x, ws, w4, b3);

    // 2) fused QKV projection: B = [wq^T|wk^T|wv^T] (384 rows), C ldc=384
    mma_gemm<32><<<dim3(3, BS / 64), 256, SMEM32>>>(x, w4, b3, qkv, 384, 384, 1);

    // 3) attention (emits bf16 av)
    attn_kernel<<<BB * HH, 256>>>(qkv, seq, av);

    // 4) output projection
    mma_gemm<32><<<dim3(1, BS / 64), 256, SMEM32>>>(av, w4 + 3 * DD * DD,
                                                    bo, enc, DD, DD, 1);

    // 5) pooling (emits bf16 p)
    pool_kernel<<<BB, 128>>>(enc, w_enc, b_enc, p);

    // 6) novelty scores: N-tile 256, grid (391, 2), 4 M-tiles per CTA
    mma_gemm<64><<<dim3(VV_PAD / 256, 2), 256, SMEM64>>>(p, ws, bscore, out,
                                                         (long long)VV, VV, 4);

    // 7) consumed mask
    mask_kernel<<<BB, 64>>>(seq, out);
}